// round 10
// baseline (speedup 1.0000x reference)
#include <cuda_runtime.h>
#include <cstdint>

#define G 512
#define NCELLS (G*G)
#define NBOX (NCELLS*2)
#define NBINS 4096
#define WIN 256
#define SORTC 512
#define CAP 512
#define SLOTS (CAP/32)
#define MAXW 2052
#define MAX_OUT 100
#define LIMIT 16384
#define SORTPAD (LIMIT + 4096)

// ---------------- device scratch ----------------
__device__ unsigned long long g_ckey[NBOX];      // compact candidate keys (unordered)
__device__ int    g_ncand;
__device__ unsigned long long g_sorted[SORTPAD]; // binned keys
__device__ int    g_hist[NBINS];
__device__ int    g_cnt[NBINS];
__device__ int    g_binStart[NBINS];
__device__ int    g_B[MAXW];
__device__ int    g_total;
__device__ int    g_S;
__device__ int    g_sidx[SORTC];
__device__ float  g_sarea[SORTC];
__device__ float  g_sscore[SORTC];
__device__ unsigned g_mat[SORTC*16];

__device__ __forceinline__ bool iou_gt(float4 a, float aa, float4 b, float ab){
    float ix1 = fmaxf(a.x, b.x);
    float iy1 = fmaxf(a.y, b.y);
    float ix2 = fminf(a.z, b.z);
    float iy2 = fminf(a.w, b.w);
    float iw  = fmaxf(__fsub_rn(ix2, ix1), 0.0f);
    float ih  = fmaxf(__fsub_rn(iy2, iy1), 0.0f);
    float inter = __fmul_rn(iw, ih);
    float den   = __fadd_rn(__fsub_rn(__fadd_rn(aa, ab), inter), 1e-9f);
    return __fdiv_rn(inter, den) > 0.5f;
}

__device__ __forceinline__ bool is_deg(float a){
    float sden = __fadd_rn(__fsub_rn(__fadd_rn(a, a), a), 1e-9f);
    return !(__fdiv_rn(a, sden) > 0.5f);
}

__device__ __forceinline__ unsigned long long shflx_u64(unsigned long long v, int m){
    return __shfl_xor_sync(0xFFFFFFFFu, v, m);
}

// exact replica of the reference box decode (op-for-op)
__device__ __forceinline__ float4 boxOf(const float* __restrict__ in, int idx, int sq, float& area){
    int cell = idx >> 1, a = idx & 1;
    int i = cell >> 9, j = cell & (G-1);
    const float* p = in + (size_t)cell*100 + 2 + 4*a;
    float rcx = p[0], rcy = p[1], w = p[2], h = p[3];
    float cx = __fmul_rn(__fadd_rn(rcx, (float)j), 16.0f);
    float cy = __fmul_rn(__fadd_rn(rcy, (float)i), 16.0f);
    if (sq){ w = __fmul_rn(w, w); h = __fmul_rn(h, h); }
    w = __fmul_rn(w, 8192.0f);
    h = __fmul_rn(h, 8192.0f);
    float hw = __fmul_rn(w, 0.5f), hh = __fmul_rn(h, 0.5f);
    float x1 = __fsub_rn(cx, hw);
    float y1 = __fsub_rn(cy, hh);
    float x2 = __fsub_rn(__fadd_rn(cx, hw), 1.0f);
    float y2 = __fsub_rn(__fadd_rn(cy, hh), 1.0f);
    area = __fmul_rn(fmaxf(__fsub_rn(x2, x1), 0.0f), fmaxf(__fsub_rn(y2, y1), 0.0f));
    return make_float4(x1, y1, x2, y2);
}

// ---------------- K1: decode scores only; append candidates + histogram ----------
__global__ void k_decode(const float* __restrict__ in){
    int gt   = blockIdx.x*blockDim.x + threadIdx.x;   // NCELLS*4 threads
    int lane = threadIdx.x & 31;
    int q    = lane & 3;
    int cell = gt >> 2;
    const float4* p = reinterpret_cast<const float4*>(in) + (size_t)cell*25;

    float4 v[7];
    #pragma unroll
    for (int s = 0; s < 7; s++){
        int r = q + 4*s;
        v[s] = (r < 25) ? p[r] : make_float4(0.f,0.f,0.f,0.f);
    }
    // per-lane class max (channels >= 10)
    float m = -1.0f;
    #pragma unroll
    for (int s = 0; s < 7; s++){
        int r = q + 4*s;
        if (r >= 25) continue;
        int c0 = 4*r;
        float4 vv = v[s];
        if (c0+0 >= 10) m = fmaxf(m, vv.x);
        if (c0+1 >= 10) m = fmaxf(m, vv.y);
        if (c0+2 >= 10) m = fmaxf(m, vv.z);
        if (c0+3 >= 10) m = fmaxf(m, vv.w);
    }
    m = fmaxf(m, __shfl_xor_sync(0xFFFFFFFFu, m, 1));
    m = fmaxf(m, __shfl_xor_sync(0xFFFFFFFFu, m, 2));

    int gbase = lane & ~3;
    float obj0 = __shfl_sync(0xFFFFFFFFu, v[0].x, gbase);
    float obj1 = __shfl_sync(0xFFFFFFFFu, v[0].y, gbase);

    bool want = false;
    float sc = 0.0f;
    int idx = 0;
    if (q == 1){ sc = __fmul_rn(m, obj0); idx = cell*2;     want = sc > 0.6f; }
    if (q == 2){ sc = __fmul_rn(m, obj1); idx = cell*2 + 1; want = sc > 0.6f; }

    unsigned bal = __ballot_sync(0xFFFFFFFFu, want);
    if (bal){
        int leader = __ffs(bal) - 1;
        int base = 0;
        if (lane == leader) base = atomicAdd(&g_ncand, __popc(bal));
        base = __shfl_sync(0xFFFFFFFFu, base, leader);
        if (want){
            int pos = base + __popc(bal & ((1u << lane) - 1u));
            unsigned bits = __float_as_uint(sc);       // sc > 0 -> raw bits monotone
            g_ckey[pos] = ((unsigned long long)bits << 32)
                        | (unsigned long long)(0xFFFFFFFFu - (unsigned)idx);
            atomicAdd(&g_hist[(bits - 0x3F000000u) >> 11], 1);
        }
    }
}

// ---------------- K2: suffix-sum + windows; zeroes hist (next replay) & cnt ------
__global__ void k_scan(){
    __shared__ int smi[NBINS];
    __shared__ int warpsum[32];
    int tid = threadIdx.x;
    int lane = tid & 31;
    int wid = tid >> 5;
    const int PER = NBINS/1024;    // 4
    int base = tid*PER;
    int vals[PER];
    int run = 0;
    #pragma unroll
    for (int t = 0; t < PER; t++){
        int b = (NBINS-1) - (base + t);
        vals[t] = run;
        run += g_hist[b];
        g_hist[b] = 0;
        g_cnt[base + t] = 0;
    }
    int x = run;
    #pragma unroll
    for (int d = 1; d < 32; d <<= 1){
        int y = __shfl_up_sync(0xFFFFFFFFu, x, d);
        if (lane >= d) x += y;
    }
    if (lane == 31) warpsum[wid] = x;
    __syncthreads();
    if (wid == 0){
        int s = warpsum[lane];
        #pragma unroll
        for (int d = 1; d < 32; d <<= 1){
            int y = __shfl_up_sync(0xFFFFFFFFu, s, d);
            if (lane >= d) s += y;
        }
        warpsum[lane] = s;
    }
    __syncthreads();
    int woff  = (wid > 0) ? warpsum[wid-1] : 0;
    int texcl = woff + x - run;
    int T     = warpsum[31];
    if (T > LIMIT) T = LIMIT;
    #pragma unroll
    for (int t = 0; t < PER; t++){
        int j = base + t;
        int s = texcl + vals[t];
        smi[j] = s;
        g_binStart[(NBINS-1) - j] = s;
    }
    if (tid == 0){ g_total = T; g_B[0] = 0; }
    for (int k = tid; k < MAXW; k += 1024) if (k > 0) g_B[k] = T;
    __syncthreads();
    #pragma unroll
    for (int t = 0; t < PER; t++){
        int j = base + t;
        if (j == 0) continue;
        int s  = smi[j];
        int sp = smi[j-1];
        if (s > T) s = T;
        if (sp > T) sp = T;
        for (int k = sp/WIN + 1; k*WIN <= s && k < MAXW; k++) g_B[k] = s;
    }
    __syncthreads();
    if (tid == 0){
        int b1 = g_B[1];
        g_S = (b1 <= SORTC) ? b1 : 0;
    }
}

// ---------------- K3: bin-scatter the candidate list (below LIMIT horizon) -------
__global__ void k_scatter(){
    int n = g_ncand;
    for (int c = blockIdx.x*blockDim.x + threadIdx.x; c < n; c += gridDim.x*blockDim.x){
        unsigned long long key = g_ckey[c];
        unsigned bits = (unsigned)(key >> 32);
        unsigned b = (bits - 0x3F000000u) >> 11;
        int bs = g_binStart[b];
        if (bs < LIMIT){
            int pos = bs + atomicAdd(&g_cnt[b], 1);
            if (pos < SORTPAD) g_sorted[pos] = key;
        }
    }
}

// ---------------- K4: fused rank + suppression matrix (chip-wide, 64 CTAs) -------
__global__ void k_rankmat(const float* __restrict__ in, const int* __restrict__ sq_p){
    __shared__ unsigned long long sk[SORTC];
    __shared__ int    ssidx[SORTC];
    __shared__ unsigned ssbits[SORTC];
    __shared__ float4 ssbox[SORTC];
    __shared__ float  ssarea[SORTC];
    int S = g_S;
    if (S == 0) return;
    int tid = threadIdx.x;
    int sq = *sq_p;
    for (int c = tid; c < SORTC; c += 256)
        sk[c] = (c < S) ? g_sorted[c] : 0ULL;
    __syncthreads();
    // per-thread rank (smem broadcast reads; keys strictly distinct)
    if (tid < S){
        unsigned long long mk = sk[tid];
        int r = 0;
        for (int j2 = 0; j2 < S; j2++) r += (sk[j2] > mk);
        ssidx[r]  = (int)(0xFFFFFFFFu - (unsigned)(mk & 0xFFFFFFFFull));
        ssbits[r] = (unsigned)(mk >> 32);
    }
    __syncthreads();
    // recompute boxes (bit-exact) by sorted position
    if (tid < S){
        float area;
        float4 b = boxOf(in, ssidx[tid], sq, area);
        ssbox[tid]  = b;
        ssarea[tid] = area;
    }
    __syncthreads();
    if (blockIdx.x == 0){
        for (int c = tid; c < S; c += 256){
            g_sidx[c]   = ssidx[c];
            g_sarea[c]  = ssarea[c];
            g_sscore[c] = __uint_as_float(ssbits[c]);
        }
    }
    // matrix rows: global warp id, upper triangle only
    int gw = blockIdx.x*8 + (tid >> 5);
    int lane = tid & 31;
    if (gw < S){
        float4 br = ssbox[gw];
        float  ar = ssarea[gw];
        int NW = (S + 31) >> 5;
        int b0 = gw >> 5;
        for (int b = 0; b < NW; b++){
            unsigned w = 0;
            if (b >= b0){
                int j2 = b*32 + lane;
                bool bit = (j2 < S) && (j2 > gw) && iou_gt(ssbox[j2], ssarea[j2], br, ar);
                w = __ballot_sync(0xFFFFFFFFu, bit);
            }
            if (lane == 0) g_mat[gw*16 + b] = w;
        }
    }
}

// ---------------- K5: greedy bit-scan + fallback + output ----------------
#define O_MAT    0
#define O_SIDX   (O_MAT + SORTC*16*4)
#define O_SSC    (O_SIDX + SORTC*4)
#define O_SDEG   (O_SSC + SORTC*4)
#define O_KIDX   (O_SDEG + (SORTC/32)*4)
#define O_KSC    (O_KIDX + MAX_OUT*4)
#define O_SCLS   (O_KSC + MAX_OUT*4)
#define O_KBOX   ((O_SCLS + MAX_OUT*4 + 15) & ~15)
#define O_KAREA  (O_KBOX + MAX_OUT*16)
#define O_CBOX   ((O_KAREA + MAX_OUT*4 + 15) & ~15)
#define O_CAREA  (O_CBOX + CAP*16)
#define SMEM_FIN (O_CAREA + CAP*4 + 64)

__global__ void __launch_bounds__(512, 1)
k_final(const float* __restrict__ in, const int* __restrict__ sq_p,
        float* __restrict__ out, int out_size){
    extern __shared__ char smraw[];
    unsigned* smat   = (unsigned*)(smraw + O_MAT);
    int*      sidx   = (int*)(smraw + O_SIDX);
    float*    sscore = (float*)(smraw + O_SSC);
    unsigned* sdeg   = (unsigned*)(smraw + O_SDEG);
    int*      kidx   = (int*)(smraw + O_KIDX);
    float*    kscore = (float*)(smraw + O_KSC);
    int*      scls   = (int*)(smraw + O_SCLS);
    float4*   kbox   = (float4*)(smraw + O_KBOX);
    float*    karea  = (float*)(smraw + O_KAREA);
    float4*   cbox   = (float4*)(smraw + O_CBOX);
    float*    carea  = (float*)(smraw + O_CAREA);
    __shared__ int s_nk, s_frozen;

    int tid  = threadIdx.x;
    int lane = tid & 31;
    int S = g_S;
    int T = g_total;
    int NW = (S + 31) >> 5;
    int sq = *sq_p;

    if (tid == 0){ s_nk = 0; s_frozen = 0; }
    for (int q = tid; q < S*16; q += 512) smat[q] = g_mat[q];
    if (tid < SORTC){
        float a = 0.0f;
        if (tid < S){
            sidx[tid]   = g_sidx[tid];
            sscore[tid] = g_sscore[tid];
            a = g_sarea[tid];
        }
        bool deg = (tid < S) && is_deg(a);
        unsigned w = __ballot_sync(0xFFFFFFFFu, deg);
        if (lane == 0) sdeg[tid >> 5] = w;
    }
    __syncthreads();

    // primary greedy scan (warp 0, pure bit ops)
    if (tid < 32){
        unsigned aw = 0;
        if (lane < NW){
            int rem = S - lane*32;
            aw = (rem >= 32) ? 0xFFFFFFFFu : ((rem > 0) ? ((1u << rem) - 1u) : 0u);
        }
        int nk = 0, frozen = 0;
        while (nk < MAX_OUT){
            unsigned bal = __ballot_sync(0xFFFFFFFFu, aw != 0u);
            if (!bal) break;
            int sl  = __ffs(bal) - 1;
            unsigned w = __shfl_sync(0xFFFFFFFFu, aw, sl);
            int bit = __ffs(w) - 1;
            int c = sl*32 + bit;
            if (lane == 0){ kidx[nk] = sidx[c]; kscore[nk] = sscore[c]; }
            nk++;
            if ((sdeg[c >> 5] >> (c & 31)) & 1u){ frozen = 1; break; }
            if (lane == sl) aw &= ~(1u << bit);
            if (lane < NW)  aw &= ~smat[c*16 + lane];
        }
        if (lane == 0){ s_nk = nk; s_frozen = frozen; }
    }
    __syncthreads();

    // fallback (rare): continue exact greedy over later windows (warp 0)
    int wstart = (S > 0) ? 1 : 0;
    if (!s_frozen && s_nk < MAX_OUT && g_B[wstart] < T){
        for (int k = tid; k < s_nk; k += 512){
            float a;
            kbox[k] = boxOf(in, kidx[k], sq, a);
            karea[k] = a;
        }
        __syncthreads();
        if (tid < 32){
            int nk = s_nk, frozen = 0;
            for (int w = wstart; w < MAXW-1 && !frozen && nk < MAX_OUT; w++){
                int lo = g_B[w], hi = g_B[w+1];
                if (lo >= T) break;
                if (hi <= lo) continue;
                int size = hi - lo; if (size > CAP) size = CAP;
                unsigned long long key[SLOTS];
                unsigned am = 0;
                #pragma unroll
                for (int t = 0; t < SLOTS; t++){
                    int c = t*32 + lane;
                    unsigned long long k = (c < size) ? g_sorted[lo + c] : 0ULL;
                    key[t] = k;
                    if (k){
                        int idx = (int)(0xFFFFFFFFu - (unsigned)(k & 0xFFFFFFFFull));
                        float a;
                        cbox[c]  = boxOf(in, idx, sq, a);
                        carea[c] = a;
                        am |= (1u << t);
                    }
                }
                __syncwarp();
                #pragma unroll
                for (int t = 0; t < SLOTS; t++){
                    if (am & (1u << t)){
                        int c = t*32 + lane;
                        float4 b = cbox[c]; float ab = carea[c];
                        for (int k2 = 0; k2 < nk; k2++)
                            if (iou_gt(b, ab, kbox[k2], karea[k2])){ am &= ~(1u << t); break; }
                    }
                }
                while (true){
                    unsigned long long best = 0;
                    #pragma unroll
                    for (int t = 0; t < SLOTS; t++)
                        if (((am >> t) & 1) && key[t] > best) best = key[t];
                    #pragma unroll
                    for (int off = 16; off; off >>= 1){
                        unsigned long long o = shflx_u64(best, off);
                        if (o > best) best = o;
                    }
                    if (best == 0) break;
                    int myc = -1;
                    #pragma unroll
                    for (int t = 0; t < SLOTS; t++)
                        if (((am >> t) & 1) && key[t] == best) myc = t*32 + lane;
                    unsigned bal = __ballot_sync(0xFFFFFFFFu, myc >= 0);
                    int src  = __ffs(bal) - 1;
                    int selc = __shfl_sync(0xFFFFFFFFu, myc, src);
                    if (lane == src) am &= ~(1u << (selc >> 5));
                    float4 sb = cbox[selc]; float sa = carea[selc];
                    if (lane == 0){
                        kidx[nk]   = (int)(0xFFFFFFFFu - (unsigned)(best & 0xFFFFFFFFull));
                        kscore[nk] = __uint_as_float((unsigned)(best >> 32));
                    }
                    kbox[nk]  = sb;       // warp-uniform
                    karea[nk] = sa;
                    nk++;
                    if (is_deg(sa)){ frozen = 1; break; }
                    if (nk == MAX_OUT) break;
                    #pragma unroll
                    for (int t = 0; t < SLOTS; t++){
                        if ((am >> t) & 1){
                            int c = t*32 + lane;
                            if (iou_gt(cbox[c], carea[c], sb, sa)) am &= ~(1u << t);
                        }
                    }
                }
                __syncwarp();
            }
            if (lane == 0){ s_nk = nk; s_frozen = frozen; }
        }
        __syncthreads();
    }
    __syncthreads();

    int nk = s_nk, frozen = s_frozen;

    // class id recompute (warp-per-kept, exact first-occurrence argmax over 90)
    {
        int warp = tid >> 5;
        for (int k = warp; k < nk && k < MAX_OUT; k += 16){
            int cell = kidx[k] >> 1;
            const float* p = in + (size_t)cell*100 + 10;
            unsigned long long key = 0;
            #pragma unroll
            for (int t = 0; t < 3; t++){
                int c = lane + 32*t;
                if (c < 90){
                    unsigned bits = __float_as_uint(p[c]);   // values in [0,1): monotone
                    unsigned long long kk = ((unsigned long long)bits << 32)
                                          | (0xFFFFFFFFu - (unsigned)c);
                    if (kk > key) key = kk;
                }
            }
            #pragma unroll
            for (int off = 16; off; off >>= 1){
                unsigned long long o = shflx_u64(key, off);
                if (o > key) key = o;
            }
            if (lane == 0) scls[k] = (int)(0xFFFFFFFFu - (unsigned)(key & 0xFFFFFFFFull));
        }
    }
    __syncthreads();

    // output [boxes(100,4) | cls_ids(100) | scores(100) | valid(100)] f32
    if (tid < MAX_OUT){
        int k = tid;
        int src = (k < nk) ? k : (frozen ? nk - 1 : -1);
        if (src >= 0){
            float a;
            float4 b = boxOf(in, kidx[src], sq, a);
            if (k*4+3 < out_size){
                out[k*4+0] = b.x; out[k*4+1] = b.y; out[k*4+2] = b.z; out[k*4+3] = b.w;
            }
            if (400+k < out_size) out[400+k] = (float)scls[src];
            if (500+k < out_size) out[500+k] = kscore[src];
            if (600+k < out_size) out[600+k] = 1.0f;
        } else {
            if (k*4+3 < out_size){
                out[k*4+0] = 0.0f; out[k*4+1] = 0.0f; out[k*4+2] = 0.0f; out[k*4+3] = 0.0f;
            }
            if (400+k < out_size) out[400+k] = -1.0f;
            if (500+k < out_size) out[500+k] = 0.0f;
            if (600+k < out_size) out[600+k] = 0.0f;
        }
    }
    if (tid == 511) g_ncand = 0;   // ready for next graph replay
}

// ---------------- fallback: extract_boxes == 0 -> raw den_boxes ----------------
__global__ void k_rawboxes(const float* __restrict__ in, const int* __restrict__ sq_p,
                           float* __restrict__ out){
    int cell = blockIdx.x*blockDim.x + threadIdx.x;
    if (cell >= NCELLS) return;
    int i = cell >> 9, j = cell & (G-1);
    const float4* p = reinterpret_cast<const float4*>(in + (size_t)cell*100);
    float4 v0 = p[0]; float4 v1 = p[1]; float4 v2 = p[2];
    int sq = *sq_p;
    float jf = (float)j, iff = (float)i;
    float rcx[2] = {v0.z, v1.z}, rcy[2] = {v0.w, v1.w};
    float rw[2]  = {v1.x, v2.x}, rh[2]  = {v1.y, v2.y};
    #pragma unroll
    for (int a = 0; a < 2; a++){
        float cx = __fmul_rn(__fadd_rn(rcx[a], jf), 16.0f);
        float cy = __fmul_rn(__fadd_rn(rcy[a], iff), 16.0f);
        float w = rw[a], h = rh[a];
        if (sq){ w = __fmul_rn(w, w); h = __fmul_rn(h, h); }
        w = __fmul_rn(w, 8192.0f);
        h = __fmul_rn(h, 8192.0f);
        int idx = cell*2 + a;
        ((float4*)out)[idx] = make_float4(cx, cy, w, h);
    }
}

// ---------------- launch ----------------
extern "C" void kernel_launch(void* const* d_in, const int* in_sizes, int n_in,
                              void* d_out, int out_size){
    const float* in = (const float*)d_in[0];
    const int*   sq = (const int*)d_in[1];

    if (out_size >= NBOX*4){
        k_rawboxes<<<NCELLS/256, 256>>>(in, sq, (float*)d_out);
        return;
    }

    cudaFuncSetAttribute(k_final, cudaFuncAttributeMaxDynamicSharedMemorySize, SMEM_FIN);

    k_decode<<<(NCELLS*4)/256, 256>>>(in);
    k_scan<<<1, 1024>>>();
    k_scatter<<<256, 256>>>();
    k_rankmat<<<64, 256>>>(in, sq);
    k_final<<<1, 512, SMEM_FIN>>>(in, sq, (float*)d_out, out_size);
}

// round 11
// speedup vs baseline: 1.1573x; 1.1573x over previous
#include <cuda_runtime.h>
#include <cstdint>

#define G 512
#define NCELLS (G*G)
#define NBOX (NCELLS*2)
#define NBINS 4096
#define WIN 256
#define SORTC 512
#define CAP 512
#define SLOTS (CAP/32)
#define MAXW 2052
#define MAX_OUT 100
#define LIMIT 16384

// ---------------- device scratch ----------------
__device__ float4 g_box[NBOX];
__device__ float  g_area[NBOX];
__device__ float  g_score[NBOX];
__device__ unsigned long long g_sorted[LIMIT + 4096];
__device__ int    g_hist[NBINS];
__device__ int    g_cnt[NBINS];
__device__ int    g_binStart[NBINS];
__device__ int    g_B[MAXW];
__device__ int    g_total;
__device__ int    g_S;
__device__ int    g_sidx[SORTC];
__device__ float  g_sarea[SORTC];
__device__ unsigned g_mat[SORTC*16];

__device__ __forceinline__ unsigned binOf(float s){
    return (__float_as_uint(s) - 0x3F000000u) >> 11;   // 4096 bins over (0.5,1.0]
}

__device__ __forceinline__ bool iou_gt(float4 a, float aa, float4 b, float ab){
    float ix1 = fmaxf(a.x, b.x);
    float iy1 = fmaxf(a.y, b.y);
    float ix2 = fminf(a.z, b.z);
    float iy2 = fminf(a.w, b.w);
    float iw  = fmaxf(__fsub_rn(ix2, ix1), 0.0f);
    float ih  = fmaxf(__fsub_rn(iy2, iy1), 0.0f);
    float inter = __fmul_rn(iw, ih);
    float den   = __fadd_rn(__fsub_rn(__fadd_rn(aa, ab), inter), 1e-9f);
    return __fdiv_rn(inter, den) > 0.5f;
}

__device__ __forceinline__ bool is_deg(float a){
    float sden = __fadd_rn(__fsub_rn(__fadd_rn(a, a), a), 1e-9f);
    return !(__fdiv_rn(a, sden) > 0.5f);
}

__device__ __forceinline__ unsigned long long shflx_u64(unsigned long long v, int m){
    return __shfl_xor_sync(0xFFFFFFFFu, v, m);
}

// ---------------- K1: decode, 4 lanes per cell (coalesced 64B clusters) --------
__global__ void k_decode(const float* __restrict__ in, const int* __restrict__ sq_p){
    int gt   = blockIdx.x*blockDim.x + threadIdx.x;   // NCELLS*4 threads
    int lane = threadIdx.x & 31;
    int q    = lane & 3;
    int cell = gt >> 2;
    const float4* p = reinterpret_cast<const float4*>(in) + (size_t)cell*25;

    float4 v[7];
    #pragma unroll
    for (int s = 0; s < 7; s++){
        int r = q + 4*s;
        v[s] = (r < 25) ? p[r] : make_float4(0.f,0.f,0.f,0.f);
    }
    // per-lane class max (channels >= 10)
    float m = -1.0f;
    #pragma unroll
    for (int s = 0; s < 7; s++){
        int r = q + 4*s;
        if (r >= 25) continue;
        int c0 = 4*r;
        float4 vv = v[s];
        if (c0+0 >= 10) m = fmaxf(m, vv.x);
        if (c0+1 >= 10) m = fmaxf(m, vv.y);
        if (c0+2 >= 10) m = fmaxf(m, vv.z);
        if (c0+3 >= 10) m = fmaxf(m, vv.w);
    }
    m = fmaxf(m, __shfl_xor_sync(0xFFFFFFFFu, m, 1));
    m = fmaxf(m, __shfl_xor_sync(0xFFFFFFFFu, m, 2));

    int gbase = lane & ~3;
    float v0x = __shfl_sync(0xFFFFFFFFu, v[0].x, gbase);
    float v0y = __shfl_sync(0xFFFFFFFFu, v[0].y, gbase);
    float v0z = __shfl_sync(0xFFFFFFFFu, v[0].z, gbase);
    float v0w = __shfl_sync(0xFFFFFFFFu, v[0].w, gbase);
    float v1z = __shfl_sync(0xFFFFFFFFu, v[0].z, gbase+1);
    float v1w = __shfl_sync(0xFFFFFFFFu, v[0].w, gbase+1);

    if (q == 1 || q == 2){
        float obj = (q == 1) ? v0x : v0y;
        float rcx = (q == 1) ? v0z : v1z;
        float rcy = (q == 1) ? v0w : v1w;
        float w = v[0].x;
        float h = v[0].y;
        int i = cell >> 9;
        int j = cell & (G-1);
        float cx = __fmul_rn(__fadd_rn(rcx, (float)j), 16.0f);
        float cy = __fmul_rn(__fadd_rn(rcy, (float)i), 16.0f);
        int sq = *sq_p;
        if (sq){ w = __fmul_rn(w, w); h = __fmul_rn(h, h); }
        w = __fmul_rn(w, 8192.0f);
        h = __fmul_rn(h, 8192.0f);
        float hw = __fmul_rn(w, 0.5f), hh = __fmul_rn(h, 0.5f);
        float x1 = __fsub_rn(cx, hw);
        float y1 = __fsub_rn(cy, hh);
        float x2 = __fsub_rn(__fadd_rn(cx, hw), 1.0f);
        float y2 = __fsub_rn(__fadd_rn(cy, hh), 1.0f);
        float area = __fmul_rn(fmaxf(__fsub_rn(x2, x1), 0.0f),
                               fmaxf(__fsub_rn(y2, y1), 0.0f));
        float sc = __fmul_rn(m, obj);
        int idx = cell*2 + (q - 1);
        g_box[idx]   = make_float4(x1, y1, x2, y2);
        g_area[idx]  = area;
        g_score[idx] = sc;
        if (sc > 0.6f) atomicAdd(&g_hist[binOf(sc)], 1);
    }
}

// ---------------- K2: suffix-sum + windows; zeroes hist (next replay) & cnt ------
__global__ void k_scan(){
    __shared__ int smi[NBINS];
    __shared__ int warpsum[32];
    int tid = threadIdx.x;
    int lane = tid & 31;
    int wid = tid >> 5;
    const int PER = NBINS/1024;    // 4
    int base = tid*PER;
    int vals[PER];
    int run = 0;
    #pragma unroll
    for (int t = 0; t < PER; t++){
        int b = (NBINS-1) - (base + t);
        vals[t] = run;
        run += g_hist[b];
        g_hist[b] = 0;
        g_cnt[base + t] = 0;
    }
    int x = run;
    #pragma unroll
    for (int d = 1; d < 32; d <<= 1){
        int y = __shfl_up_sync(0xFFFFFFFFu, x, d);
        if (lane >= d) x += y;
    }
    if (lane == 31) warpsum[wid] = x;
    __syncthreads();
    if (wid == 0){
        int s = warpsum[lane];
        #pragma unroll
        for (int d = 1; d < 32; d <<= 1){
            int y = __shfl_up_sync(0xFFFFFFFFu, s, d);
            if (lane >= d) s += y;
        }
        warpsum[lane] = s;
    }
    __syncthreads();
    int woff  = (wid > 0) ? warpsum[wid-1] : 0;
    int texcl = woff + x - run;
    int T     = warpsum[31];
    if (T > LIMIT) T = LIMIT;
    #pragma unroll
    for (int t = 0; t < PER; t++){
        int j = base + t;
        int s = texcl + vals[t];
        smi[j] = s;
        g_binStart[(NBINS-1) - j] = s;
    }
    if (tid == 0){ g_total = T; g_B[0] = 0; }
    for (int k = tid; k < MAXW; k += 1024) if (k > 0) g_B[k] = T;
    __syncthreads();
    #pragma unroll
    for (int t = 0; t < PER; t++){
        int j = base + t;
        if (j == 0) continue;
        int s  = smi[j];
        int sp = smi[j-1];
        if (s > T) s = T;
        if (sp > T) sp = T;
        for (int k = sp/WIN + 1; k*WIN <= s && k < MAXW; k++) g_B[k] = s;
    }
    __syncthreads();
    if (tid == 0){
        int b1 = g_B[1];
        g_S = (b1 <= SORTC) ? b1 : 0;
    }
}

// ---------------- K3: compact candidates (only below LIMIT horizon) ------------
__global__ void k_scatter(){
    int idx = blockIdx.x*blockDim.x + threadIdx.x;
    if (idx >= NBOX) return;
    float s = g_score[idx];
    if (s > 0.6f){
        unsigned b = binOf(s);
        int bs = g_binStart[b];
        if (bs < LIMIT){
            int pos = bs + atomicAdd(&g_cnt[b], 1);
            unsigned long long key = ((unsigned long long)__float_as_uint(s) << 32)
                                   | (unsigned long long)(0xFFFFFFFFu - (unsigned)idx);
            g_sorted[pos] = key;
        }
    }
}

// ---------------- K4: fused rank + suppression matrix (chip-wide, 64 CTAs) -------
__global__ void k_rankmat(){
    __shared__ unsigned long long sk[SORTC];
    __shared__ int    ssidx[SORTC];
    __shared__ float4 ssbox[SORTC];
    __shared__ float  ssarea[SORTC];
    int S = g_S;
    if (S == 0) return;
    int tid = threadIdx.x;
    for (int c = tid; c < SORTC; c += 256)
        sk[c] = (c < S) ? g_sorted[c] : 0ULL;
    __syncthreads();
    // per-thread rank (smem broadcast reads; keys strictly distinct)
    for (int c = tid; c < S; c += 256){
        unsigned long long mk = sk[c];
        int r = 0;
        for (int j2 = 0; j2 < S; j2++) r += (sk[j2] > mk);
        ssidx[r] = (int)(0xFFFFFFFFu - (unsigned)(mk & 0xFFFFFFFFull));
    }
    __syncthreads();
    // gather boxes by sorted position
    for (int c = tid; c < S; c += 256){
        int idx = ssidx[c];
        ssbox[c]  = g_box[idx];
        ssarea[c] = g_area[idx];
    }
    __syncthreads();
    if (blockIdx.x == 0){
        for (int c = tid; c < S; c += 256){
            g_sidx[c]  = ssidx[c];
            g_sarea[c] = ssarea[c];
        }
    }
    // matrix rows: global warp id, upper triangle only
    int gw = blockIdx.x*8 + (tid >> 5);
    int lane = tid & 31;
    if (gw < S){
        float4 br = ssbox[gw];
        float  ar = ssarea[gw];
        int NW = (S + 31) >> 5;
        int b0 = gw >> 5;
        for (int b = 0; b < NW; b++){
            unsigned w = 0;
            if (b >= b0){
                int j2 = b*32 + lane;
                bool bit = (j2 < S) && (j2 > gw) && iou_gt(ssbox[j2], ssarea[j2], br, ar);
                w = __ballot_sync(0xFFFFFFFFu, bit);
            }
            if (lane == 0) g_mat[gw*16 + b] = w;
        }
    }
}

// ---------------- K5: greedy bit-scan + fallback + output ----------------
#define O_MAT    0
#define O_SIDX   (O_MAT + SORTC*16*4)
#define O_SDEG   (O_SIDX + SORTC*4)
#define O_KIDX   (O_SDEG + (SORTC/32)*4)
#define O_SCLS   (O_KIDX + MAX_OUT*4)
#define O_KBOX   ((O_SCLS + MAX_OUT*4 + 15) & ~15)
#define O_KAREA  (O_KBOX + MAX_OUT*16)
#define O_CBOX   ((O_KAREA + MAX_OUT*4 + 15) & ~15)
#define O_CAREA  (O_CBOX + CAP*16)
#define SMEM_FIN (O_CAREA + CAP*4 + 64)

__global__ void __launch_bounds__(512, 1)
k_final(const float* __restrict__ in, float* __restrict__ out, int out_size){
    extern __shared__ char smraw[];
    unsigned* smat  = (unsigned*)(smraw + O_MAT);
    int*      sidx  = (int*)(smraw + O_SIDX);
    unsigned* sdeg  = (unsigned*)(smraw + O_SDEG);
    int*      kidx  = (int*)(smraw + O_KIDX);
    int*      scls  = (int*)(smraw + O_SCLS);
    float4*   kbox  = (float4*)(smraw + O_KBOX);
    float*    karea = (float*)(smraw + O_KAREA);
    float4*   cbox  = (float4*)(smraw + O_CBOX);
    float*    carea = (float*)(smraw + O_CAREA);
    __shared__ int s_nk, s_frozen;

    int tid  = threadIdx.x;
    int lane = tid & 31;
    int S = g_S;
    int T = g_total;
    int NW = (S + 31) >> 5;

    if (tid == 0){ s_nk = 0; s_frozen = 0; }
    for (int q = tid; q < S*16; q += 512) smat[q] = g_mat[q];
    if (tid < SORTC){
        float a = 0.0f;
        if (tid < S){
            sidx[tid] = g_sidx[tid];
            a = g_sarea[tid];
        }
        bool deg = (tid < S) && is_deg(a);
        unsigned w = __ballot_sync(0xFFFFFFFFu, deg);
        if (lane == 0) sdeg[tid >> 5] = w;
    }
    __syncthreads();

    // primary greedy scan (warp 0, pure bit ops)
    if (tid < 32){
        unsigned aw = 0;
        if (lane < NW){
            int rem = S - lane*32;
            aw = (rem >= 32) ? 0xFFFFFFFFu : ((rem > 0) ? ((1u << rem) - 1u) : 0u);
        }
        int nk = 0, frozen = 0;
        while (nk < MAX_OUT){
            unsigned bal = __ballot_sync(0xFFFFFFFFu, aw != 0u);
            if (!bal) break;
            int sl  = __ffs(bal) - 1;
            unsigned w = __shfl_sync(0xFFFFFFFFu, aw, sl);
            int bit = __ffs(w) - 1;
            int c = sl*32 + bit;
            if (lane == 0) kidx[nk] = sidx[c];
            nk++;
            if ((sdeg[c >> 5] >> (c & 31)) & 1u){ frozen = 1; break; }
            if (lane == sl) aw &= ~(1u << bit);
            if (lane < NW)  aw &= ~smat[c*16 + lane];
        }
        if (lane == 0){ s_nk = nk; s_frozen = frozen; }
    }
    __syncthreads();

    // fallback (rare): continue exact greedy over later windows (warp 0)
    int wstart = (S > 0) ? 1 : 0;
    if (!s_frozen && s_nk < MAX_OUT && g_B[wstart] < T){
        for (int k = tid; k < s_nk; k += 512){
            int idx = kidx[k];
            kbox[k]  = g_box[idx];
            karea[k] = g_area[idx];
        }
        __syncthreads();
        if (tid < 32){
            int nk = s_nk, frozen = 0;
            for (int w = wstart; w < MAXW-1 && !frozen && nk < MAX_OUT; w++){
                int lo = g_B[w], hi = g_B[w+1];
                if (lo >= T) break;
                if (hi <= lo) continue;
                int size = hi - lo; if (size > CAP) size = CAP;
                unsigned long long key[SLOTS];
                unsigned am = 0;
                #pragma unroll
                for (int t = 0; t < SLOTS; t++){
                    int c = t*32 + lane;
                    unsigned long long k = (c < size) ? g_sorted[lo + c] : 0ULL;
                    key[t] = k;
                    if (k){
                        unsigned idx = 0xFFFFFFFFu - (unsigned)(k & 0xFFFFFFFFull);
                        cbox[c]  = g_box[idx];
                        carea[c] = g_area[idx];
                        am |= (1u << t);
                    }
                }
                __syncwarp();
                #pragma unroll
                for (int t = 0; t < SLOTS; t++){
                    if (am & (1u << t)){
                        int c = t*32 + lane;
                        float4 b = cbox[c]; float ab = carea[c];
                        for (int k2 = 0; k2 < nk; k2++)
                            if (iou_gt(b, ab, kbox[k2], karea[k2])){ am &= ~(1u << t); break; }
                    }
                }
                while (true){
                    unsigned long long best = 0;
                    #pragma unroll
                    for (int t = 0; t < SLOTS; t++)
                        if (((am >> t) & 1) && key[t] > best) best = key[t];
                    #pragma unroll
                    for (int off = 16; off; off >>= 1){
                        unsigned long long o = shflx_u64(best, off);
                        if (o > best) best = o;
                    }
                    if (best == 0) break;
                    int myc = -1;
                    #pragma unroll
                    for (int t = 0; t < SLOTS; t++)
                        if (((am >> t) & 1) && key[t] == best) myc = t*32 + lane;
                    unsigned bal = __ballot_sync(0xFFFFFFFFu, myc >= 0);
                    int src  = __ffs(bal) - 1;
                    int selc = __shfl_sync(0xFFFFFFFFu, myc, src);
                    if (lane == src) am &= ~(1u << (selc >> 5));
                    float4 sb = cbox[selc]; float sa = carea[selc];
                    if (lane == 0) kidx[nk] = (int)(0xFFFFFFFFu - (unsigned)(best & 0xFFFFFFFFull));
                    kbox[nk]  = sb;     // warp-uniform
                    karea[nk] = sa;
                    nk++;
                    if (is_deg(sa)){ frozen = 1; break; }
                    if (nk == MAX_OUT) break;
                    #pragma unroll
                    for (int t = 0; t < SLOTS; t++){
                        if ((am >> t) & 1){
                            int c = t*32 + lane;
                            if (iou_gt(cbox[c], carea[c], sb, sa)) am &= ~(1u << t);
                        }
                    }
                }
                __syncwarp();
            }
            if (lane == 0){ s_nk = nk; s_frozen = frozen; }
        }
        __syncthreads();
    }
    __syncthreads();

    int nk = s_nk, frozen = s_frozen;

    // class id recompute for kept boxes (warp-per-kept, exact first-occurrence argmax)
    {
        int warp = tid >> 5;
        for (int k = warp; k < nk && k < MAX_OUT; k += 16){
            int cell = kidx[k] >> 1;
            const float* p = in + (size_t)cell*100 + 10;
            unsigned long long key = 0;
            #pragma unroll
            for (int t = 0; t < 3; t++){
                int c = lane + 32*t;
                if (c < 90){
                    unsigned bits = __float_as_uint(p[c]);   // values in [0,1): monotone
                    unsigned long long kk = ((unsigned long long)bits << 32)
                                          | (0xFFFFFFFFu - (unsigned)c);
                    if (kk > key) key = kk;
                }
            }
            #pragma unroll
            for (int off = 16; off; off >>= 1){
                unsigned long long o = shflx_u64(key, off);
                if (o > key) key = o;
            }
            if (lane == 0) scls[k] = (int)(0xFFFFFFFFu - (unsigned)(key & 0xFFFFFFFFull));
        }
    }
    __syncthreads();

    // output [boxes(100,4) | cls_ids(100) | scores(100) | valid(100)] f32
    if (tid < MAX_OUT){
        int k = tid;
        int src = (k < nk) ? k : (frozen ? nk - 1 : -1);
        if (src >= 0){
            int idx = kidx[src];
            float4 b = g_box[idx];
            if (k*4+3 < out_size){
                out[k*4+0] = b.x; out[k*4+1] = b.y; out[k*4+2] = b.z; out[k*4+3] = b.w;
            }
            if (400+k < out_size) out[400+k] = (float)scls[src];
            if (500+k < out_size) out[500+k] = g_score[idx];
            if (600+k < out_size) out[600+k] = 1.0f;
        } else {
            if (k*4+3 < out_size){
                out[k*4+0] = 0.0f; out[k*4+1] = 0.0f; out[k*4+2] = 0.0f; out[k*4+3] = 0.0f;
            }
            if (400+k < out_size) out[400+k] = -1.0f;
            if (500+k < out_size) out[500+k] = 0.0f;
            if (600+k < out_size) out[600+k] = 0.0f;
        }
    }
}

// ---------------- fallback: extract_boxes == 0 -> raw den_boxes ----------------
__global__ void k_rawboxes(const float* __restrict__ in, const int* __restrict__ sq_p,
                           float* __restrict__ out){
    int cell = blockIdx.x*blockDim.x + threadIdx.x;
    if (cell >= NCELLS) return;
    int i = cell >> 9, j = cell & (G-1);
    const float4* p = reinterpret_cast<const float4*>(in + (size_t)cell*100);
    float4 v0 = p[0]; float4 v1 = p[1]; float4 v2 = p[2];
    int sq = *sq_p;
    float jf = (float)j, iff = (float)i;
    float rcx[2] = {v0.z, v1.z}, rcy[2] = {v0.w, v1.w};
    float rw[2]  = {v1.x, v2.x}, rh[2]  = {v1.y, v2.y};
    #pragma unroll
    for (int a = 0; a < 2; a++){
        float cx = __fmul_rn(__fadd_rn(rcx[a], jf), 16.0f);
        float cy = __fmul_rn(__fadd_rn(rcy[a], iff), 16.0f);
        float w = rw[a], h = rh[a];
        if (sq){ w = __fmul_rn(w, w); h = __fmul_rn(h, h); }
        w = __fmul_rn(w, 8192.0f);
        h = __fmul_rn(h, 8192.0f);
        int idx = cell*2 + a;
        ((float4*)out)[idx] = make_float4(cx, cy, w, h);
    }
}

// ---------------- launch ----------------
extern "C" void kernel_launch(void* const* d_in, const int* in_sizes, int n_in,
                              void* d_out, int out_size){
    const float* in = (const float*)d_in[0];
    const int*   sq = (const int*)d_in[1];

    if (out_size >= NBOX*4){
        k_rawboxes<<<NCELLS/256, 256>>>(in, sq, (float*)d_out);
        return;
    }

    cudaFuncSetAttribute(k_final, cudaFuncAttributeMaxDynamicSharedMemorySize, SMEM_FIN);

    k_decode<<<(NCELLS*4)/256, 256>>>(in, sq);
    k_scan<<<1, 1024>>>();
    k_scatter<<<NBOX/256, 256>>>();
    k_rankmat<<<64, 256>>>();
    k_final<<<1, 512, SMEM_FIN>>>(in, (float*)d_out, out_size);
}

// round 12
// speedup vs baseline: 1.2569x; 1.0861x over previous
#include <cuda_runtime.h>
#include <cstdint>

#define G 512
#define NCELLS (G*G)
#define NBOX (NCELLS*2)
#define NBINS 4096
#define WIN 256
#define SORTC 512
#define CAP 512
#define SLOTS (CAP/32)
#define MAXW 2052
#define MAX_OUT 100
#define LIMIT 16384

// ---------------- device scratch ----------------
__device__ float4 g_box[NBOX];
__device__ float  g_area[NBOX];
__device__ float  g_score[NBOX];
__device__ unsigned long long g_sorted[LIMIT + 4096];
__device__ int    g_hist[NBINS];
__device__ int    g_cnt[NBINS];
__device__ int    g_binStart[NBINS];
__device__ int    g_B[MAXW];
__device__ int    g_total;
__device__ int    g_S;
__device__ int    g_sidx[SORTC];
__device__ float4 g_sbox[SORTC];
__device__ float  g_sarea[SORTC];
__device__ unsigned g_mat[SORTC*16];

__device__ __forceinline__ unsigned binOf(float s){
    return (__float_as_uint(s) - 0x3F000000u) >> 11;   // 4096 bins over (0.5,1.0]
}

__device__ __forceinline__ bool iou_gt(float4 a, float aa, float4 b, float ab){
    float ix1 = fmaxf(a.x, b.x);
    float iy1 = fmaxf(a.y, b.y);
    float ix2 = fminf(a.z, b.z);
    float iy2 = fminf(a.w, b.w);
    float iw  = fmaxf(__fsub_rn(ix2, ix1), 0.0f);
    float ih  = fmaxf(__fsub_rn(iy2, iy1), 0.0f);
    float inter = __fmul_rn(iw, ih);
    float den   = __fadd_rn(__fsub_rn(__fadd_rn(aa, ab), inter), 1e-9f);
    return __fdiv_rn(inter, den) > 0.5f;
}

__device__ __forceinline__ bool is_deg(float a){
    float sden = __fadd_rn(__fsub_rn(__fadd_rn(a, a), a), 1e-9f);
    return !(__fdiv_rn(a, sden) > 0.5f);
}

__device__ __forceinline__ unsigned long long shflx_u64(unsigned long long v, int m){
    return __shfl_xor_sync(0xFFFFFFFFu, v, m);
}

// ---------------- K1: decode, 4 lanes per cell (coalesced 64B clusters) --------
__global__ void k_decode(const float* __restrict__ in, const int* __restrict__ sq_p){
    cudaGridDependencySynchronize();   // PDL: wait prior replay's k_final before writing g_box
    int gt   = blockIdx.x*blockDim.x + threadIdx.x;   // NCELLS*4 threads
    int lane = threadIdx.x & 31;
    int q    = lane & 3;
    int cell = gt >> 2;
    const float4* p = reinterpret_cast<const float4*>(in) + (size_t)cell*25;

    float4 v[7];
    #pragma unroll
    for (int s = 0; s < 7; s++){
        int r = q + 4*s;
        v[s] = (r < 25) ? p[r] : make_float4(0.f,0.f,0.f,0.f);
    }
    // per-lane class max (channels >= 10)
    float m = -1.0f;
    #pragma unroll
    for (int s = 0; s < 7; s++){
        int r = q + 4*s;
        if (r >= 25) continue;
        int c0 = 4*r;
        float4 vv = v[s];
        if (c0+0 >= 10) m = fmaxf(m, vv.x);
        if (c0+1 >= 10) m = fmaxf(m, vv.y);
        if (c0+2 >= 10) m = fmaxf(m, vv.z);
        if (c0+3 >= 10) m = fmaxf(m, vv.w);
    }
    m = fmaxf(m, __shfl_xor_sync(0xFFFFFFFFu, m, 1));
    m = fmaxf(m, __shfl_xor_sync(0xFFFFFFFFu, m, 2));

    int gbase = lane & ~3;
    float v0x = __shfl_sync(0xFFFFFFFFu, v[0].x, gbase);
    float v0y = __shfl_sync(0xFFFFFFFFu, v[0].y, gbase);
    float v0z = __shfl_sync(0xFFFFFFFFu, v[0].z, gbase);
    float v0w = __shfl_sync(0xFFFFFFFFu, v[0].w, gbase);
    float v1z = __shfl_sync(0xFFFFFFFFu, v[0].z, gbase+1);
    float v1w = __shfl_sync(0xFFFFFFFFu, v[0].w, gbase+1);

    if (q == 1 || q == 2){
        float obj = (q == 1) ? v0x : v0y;
        float rcx = (q == 1) ? v0z : v1z;
        float rcy = (q == 1) ? v0w : v1w;
        float w = v[0].x;
        float h = v[0].y;
        int i = cell >> 9;
        int j = cell & (G-1);
        float cx = __fmul_rn(__fadd_rn(rcx, (float)j), 16.0f);
        float cy = __fmul_rn(__fadd_rn(rcy, (float)i), 16.0f);
        int sq = *sq_p;
        if (sq){ w = __fmul_rn(w, w); h = __fmul_rn(h, h); }
        w = __fmul_rn(w, 8192.0f);
        h = __fmul_rn(h, 8192.0f);
        float hw = __fmul_rn(w, 0.5f), hh = __fmul_rn(h, 0.5f);
        float x1 = __fsub_rn(cx, hw);
        float y1 = __fsub_rn(cy, hh);
        float x2 = __fsub_rn(__fadd_rn(cx, hw), 1.0f);
        float y2 = __fsub_rn(__fadd_rn(cy, hh), 1.0f);
        float area = __fmul_rn(fmaxf(__fsub_rn(x2, x1), 0.0f),
                               fmaxf(__fsub_rn(y2, y1), 0.0f));
        float sc = __fmul_rn(m, obj);
        int idx = cell*2 + (q - 1);
        g_box[idx]   = make_float4(x1, y1, x2, y2);
        g_area[idx]  = area;
        g_score[idx] = sc;
        if (sc > 0.6f) atomicAdd(&g_hist[binOf(sc)], 1);
    }
}

// ---------------- K2: suffix-sum + windows; zeroes hist (next replay) & cnt ------
__global__ void k_scan(){
    __shared__ int smi[NBINS];
    __shared__ int warpsum[32];
    cudaGridDependencySynchronize();
    int tid = threadIdx.x;
    int lane = tid & 31;
    int wid = tid >> 5;
    const int PER = NBINS/1024;    // 4
    int base = tid*PER;
    int vals[PER];
    int run = 0;
    #pragma unroll
    for (int t = 0; t < PER; t++){
        int b = (NBINS-1) - (base + t);
        vals[t] = run;
        run += g_hist[b];
        g_hist[b] = 0;
        g_cnt[base + t] = 0;
    }
    int x = run;
    #pragma unroll
    for (int d = 1; d < 32; d <<= 1){
        int y = __shfl_up_sync(0xFFFFFFFFu, x, d);
        if (lane >= d) x += y;
    }
    if (lane == 31) warpsum[wid] = x;
    __syncthreads();
    if (wid == 0){
        int s = warpsum[lane];
        #pragma unroll
        for (int d = 1; d < 32; d <<= 1){
            int y = __shfl_up_sync(0xFFFFFFFFu, s, d);
            if (lane >= d) s += y;
        }
        warpsum[lane] = s;
    }
    __syncthreads();
    int woff  = (wid > 0) ? warpsum[wid-1] : 0;
    int texcl = woff + x - run;
    int T     = warpsum[31];
    if (T > LIMIT) T = LIMIT;
    #pragma unroll
    for (int t = 0; t < PER; t++){
        int j = base + t;
        int s = texcl + vals[t];
        smi[j] = s;
        g_binStart[(NBINS-1) - j] = s;
    }
    if (tid == 0){ g_total = T; g_B[0] = 0; }
    for (int k = tid; k < MAXW; k += 1024) if (k > 0) g_B[k] = T;
    __syncthreads();
    #pragma unroll
    for (int t = 0; t < PER; t++){
        int j = base + t;
        if (j == 0) continue;
        int s  = smi[j];
        int sp = smi[j-1];
        if (s > T) s = T;
        if (sp > T) sp = T;
        for (int k = sp/WIN + 1; k*WIN <= s && k < MAXW; k++) g_B[k] = s;
    }
    __syncthreads();
    if (tid == 0){
        int b1 = g_B[1];
        g_S = (b1 <= SORTC) ? b1 : 0;
    }
}

// ---------------- K3: compact candidates (only below LIMIT horizon) ------------
__global__ void k_scatter(){
    cudaGridDependencySynchronize();
    int idx = blockIdx.x*blockDim.x + threadIdx.x;
    if (idx >= NBOX) return;
    float s = g_score[idx];
    if (s > 0.6f){
        unsigned b = binOf(s);
        int bs = g_binStart[b];
        if (bs < LIMIT){
            int pos = bs + atomicAdd(&g_cnt[b], 1);
            unsigned long long key = ((unsigned long long)__float_as_uint(s) << 32)
                                   | (unsigned long long)(0xFFFFFFFFu - (unsigned)idx);
            g_sorted[pos] = key;
        }
    }
}

// ---------------- K4: chip-wide rank (warp per key, keys staged in smem) -------
__global__ void k_rank(){
    __shared__ unsigned long long sk[SORTC];
    cudaGridDependencySynchronize();
    int S = g_S;
    int tid = threadIdx.x;
    for (int c = tid; c < SORTC; c += 256)
        sk[c] = (c < S) ? g_sorted[c] : 0ULL;
    __syncthreads();
    int w = (blockIdx.x*256 + tid) >> 5;
    int lane = tid & 31;
    if (w >= S) return;
    unsigned long long mk = sk[w];
    int NW = (S + 31) >> 5;
    int r = 0;
    for (int b = 0; b < NW; b++){
        unsigned long long kj = sk[b*32 + lane];   // 0ULL padding never > real key
        r += __popc(__ballot_sync(0xFFFFFFFFu, kj > mk));
    }
    if (lane == 0){
        int idx = (int)(0xFFFFFFFFu - (unsigned)(mk & 0xFFFFFFFFull));
        g_sidx[r]  = idx;
        g_sbox[r]  = g_box[idx];
        g_sarea[r] = g_area[idx];
    }
}

// ---------------- K5: suppression matrix (chip-wide, upper triangle) ----------
__global__ void k_matrix(){
    cudaGridDependencySynchronize();
    int r = (blockIdx.x*blockDim.x + threadIdx.x) >> 5;
    int lane = threadIdx.x & 31;
    int S = g_S;
    if (r >= S) return;
    int NW = (S + 31) >> 5;
    float4 br = g_sbox[r];
    float  ar = g_sarea[r];
    int b0 = r >> 5;
    for (int b = 0; b < NW; b++){
        unsigned w = 0;
        if (b >= b0){
            int j2 = b*32 + lane;
            bool bit = (j2 < S) && (j2 > r) && iou_gt(g_sbox[j2], g_sarea[j2], br, ar);
            w = __ballot_sync(0xFFFFFFFFu, bit);
        }
        if (lane == 0) g_mat[r*16 + b] = w;
    }
}

// ---------------- K6: greedy bit-scan + fallback + cls recompute + output -------
#define O_MAT    0
#define O_SIDX   (O_MAT + SORTC*16*4)
#define O_SDEG   (O_SIDX + SORTC*4)
#define O_KIDX   (O_SDEG + (SORTC/32)*4)
#define O_SCLS   (O_KIDX + MAX_OUT*4)
#define O_KBOX   ((O_SCLS + MAX_OUT*4 + 15) & ~15)
#define O_KAREA  (O_KBOX + MAX_OUT*16)
#define O_CBOX   ((O_KAREA + MAX_OUT*4 + 15) & ~15)
#define O_CAREA  (O_CBOX + CAP*16)
#define SMEM_FIN (O_CAREA + CAP*4 + 64)

__global__ void __launch_bounds__(512, 1)
k_final(const float* __restrict__ in, float* __restrict__ out, int out_size){
    extern __shared__ char smraw[];
    unsigned* smat  = (unsigned*)(smraw + O_MAT);
    int*      sidx  = (int*)(smraw + O_SIDX);
    unsigned* sdeg  = (unsigned*)(smraw + O_SDEG);
    int*      kidx  = (int*)(smraw + O_KIDX);
    int*      scls  = (int*)(smraw + O_SCLS);
    float4*   kbox  = (float4*)(smraw + O_KBOX);
    float*    karea = (float*)(smraw + O_KAREA);
    float4*   cbox  = (float4*)(smraw + O_CBOX);
    float*    carea = (float*)(smraw + O_CAREA);
    __shared__ int s_nk, s_frozen;

    cudaGridDependencySynchronize();
    int tid  = threadIdx.x;
    int lane = tid & 31;
    int S = g_S;
    int T = g_total;
    int NW = (S + 31) >> 5;

    if (tid == 0){ s_nk = 0; s_frozen = 0; }
    for (int q = tid; q < S*16; q += 512) smat[q] = g_mat[q];
    if (tid < SORTC){
        float a = 0.0f;
        if (tid < S){
            sidx[tid] = g_sidx[tid];
            a = g_sarea[tid];
        }
        bool deg = (tid < S) && is_deg(a);
        unsigned w = __ballot_sync(0xFFFFFFFFu, deg);
        if (lane == 0) sdeg[tid >> 5] = w;
    }
    __syncthreads();

    // primary greedy scan (warp 0, pure bit ops)
    if (tid < 32){
        unsigned aw = 0;
        if (lane < NW){
            int rem = S - lane*32;
            aw = (rem >= 32) ? 0xFFFFFFFFu : ((rem > 0) ? ((1u << rem) - 1u) : 0u);
        }
        int nk = 0, frozen = 0;
        while (nk < MAX_OUT){
            unsigned bal = __ballot_sync(0xFFFFFFFFu, aw != 0u);
            if (!bal) break;
            int sl  = __ffs(bal) - 1;
            unsigned w = __shfl_sync(0xFFFFFFFFu, aw, sl);
            int bit = __ffs(w) - 1;
            int c = sl*32 + bit;
            if (lane == 0) kidx[nk] = sidx[c];
            nk++;
            if ((sdeg[c >> 5] >> (c & 31)) & 1u){ frozen = 1; break; }
            if (lane == sl) aw &= ~(1u << bit);
            if (lane < NW)  aw &= ~smat[c*16 + lane];
        }
        if (lane == 0){ s_nk = nk; s_frozen = frozen; }
    }
    __syncthreads();

    // fallback (rare): continue exact greedy over later windows (warp 0)
    int wstart = (S > 0) ? 1 : 0;
    if (!s_frozen && s_nk < MAX_OUT && g_B[wstart] < T){
        for (int k = tid; k < s_nk; k += 512){
            int idx = kidx[k];
            kbox[k]  = g_box[idx];
            karea[k] = g_area[idx];
        }
        __syncthreads();
        if (tid < 32){
            int nk = s_nk, frozen = 0;
            for (int w = wstart; w < MAXW-1 && !frozen && nk < MAX_OUT; w++){
                int lo = g_B[w], hi = g_B[w+1];
                if (lo >= T) break;
                if (hi <= lo) continue;
                int size = hi - lo; if (size > CAP) size = CAP;
                unsigned long long key[SLOTS];
                unsigned am = 0;
                #pragma unroll
                for (int t = 0; t < SLOTS; t++){
                    int c = t*32 + lane;
                    unsigned long long k = (c < size) ? g_sorted[lo + c] : 0ULL;
                    key[t] = k;
                    if (k){
                        unsigned idx = 0xFFFFFFFFu - (unsigned)(k & 0xFFFFFFFFull);
                        cbox[c]  = g_box[idx];
                        carea[c] = g_area[idx];
                        am |= (1u << t);
                    }
                }
                __syncwarp();
                #pragma unroll
                for (int t = 0; t < SLOTS; t++){
                    if (am & (1u << t)){
                        int c = t*32 + lane;
                        float4 b = cbox[c]; float ab = carea[c];
                        for (int k2 = 0; k2 < nk; k2++)
                            if (iou_gt(b, ab, kbox[k2], karea[k2])){ am &= ~(1u << t); break; }
                    }
                }
                while (true){
                    unsigned long long best = 0;
                    #pragma unroll
                    for (int t = 0; t < SLOTS; t++)
                        if (((am >> t) & 1) && key[t] > best) best = key[t];
                    #pragma unroll
                    for (int off = 16; off; off >>= 1){
                        unsigned long long o = shflx_u64(best, off);
                        if (o > best) best = o;
                    }
                    if (best == 0) break;
                    int myc = -1;
                    #pragma unroll
                    for (int t = 0; t < SLOTS; t++)
                        if (((am >> t) & 1) && key[t] == best) myc = t*32 + lane;
                    unsigned bal = __ballot_sync(0xFFFFFFFFu, myc >= 0);
                    int src  = __ffs(bal) - 1;
                    int selc = __shfl_sync(0xFFFFFFFFu, myc, src);
                    if (lane == src) am &= ~(1u << (selc >> 5));
                    float4 sb = cbox[selc]; float sa = carea[selc];
                    if (lane == 0) kidx[nk] = (int)(0xFFFFFFFFu - (unsigned)(best & 0xFFFFFFFFull));
                    kbox[nk]  = sb;     // warp-uniform
                    karea[nk] = sa;
                    nk++;
                    if (is_deg(sa)){ frozen = 1; break; }
                    if (nk == MAX_OUT) break;
                    #pragma unroll
                    for (int t = 0; t < SLOTS; t++){
                        if ((am >> t) & 1){
                            int c = t*32 + lane;
                            if (iou_gt(cbox[c], carea[c], sb, sa)) am &= ~(1u << t);
                        }
                    }
                }
                __syncwarp();
            }
            if (lane == 0){ s_nk = nk; s_frozen = frozen; }
        }
        __syncthreads();
    }
    __syncthreads();

    int nk = s_nk, frozen = s_frozen;

    // class id recompute for kept boxes (warp-per-kept, exact first-occurrence argmax)
    {
        int warp = tid >> 5;
        for (int k = warp; k < nk && k < MAX_OUT; k += 16){
            int cell = kidx[k] >> 1;
            const float* p = in + (size_t)cell*100 + 10;
            unsigned long long key = 0;
            #pragma unroll
            for (int t = 0; t < 3; t++){
                int c = lane + 32*t;
                if (c < 90){
                    unsigned bits = __float_as_uint(p[c]);   // values in [0,1): monotone
                    unsigned long long kk = ((unsigned long long)bits << 32)
                                          | (0xFFFFFFFFu - (unsigned)c);
                    if (kk > key) key = kk;
                }
            }
            #pragma unroll
            for (int off = 16; off; off >>= 1){
                unsigned long long o = shflx_u64(key, off);
                if (o > key) key = o;
            }
            if (lane == 0) scls[k] = (int)(0xFFFFFFFFu - (unsigned)(key & 0xFFFFFFFFull));
        }
    }
    __syncthreads();

    // output [boxes(100,4) | cls_ids(100) | scores(100) | valid(100)] f32
    if (tid < MAX_OUT){
        int k = tid;
        int src = (k < nk) ? k : (frozen ? nk - 1 : -1);
        if (src >= 0){
            int idx = kidx[src];
            float4 b = g_box[idx];
            if (k*4+3 < out_size){
                out[k*4+0] = b.x; out[k*4+1] = b.y; out[k*4+2] = b.z; out[k*4+3] = b.w;
            }
            if (400+k < out_size) out[400+k] = (float)scls[src];
            if (500+k < out_size) out[500+k] = g_score[idx];
            if (600+k < out_size) out[600+k] = 1.0f;
        } else {
            if (k*4+3 < out_size){
                out[k*4+0] = 0.0f; out[k*4+1] = 0.0f; out[k*4+2] = 0.0f; out[k*4+3] = 0.0f;
            }
            if (400+k < out_size) out[400+k] = -1.0f;
            if (500+k < out_size) out[500+k] = 0.0f;
            if (600+k < out_size) out[600+k] = 0.0f;
        }
    }
}

// ---------------- fallback: extract_boxes == 0 -> raw den_boxes ----------------
__global__ void k_rawboxes(const float* __restrict__ in, const int* __restrict__ sq_p,
                           float* __restrict__ out){
    int cell = blockIdx.x*blockDim.x + threadIdx.x;
    if (cell >= NCELLS) return;
    int i = cell >> 9, j = cell & (G-1);
    const float4* p = reinterpret_cast<const float4*>(in + (size_t)cell*100);
    float4 v0 = p[0]; float4 v1 = p[1]; float4 v2 = p[2];
    int sq = *sq_p;
    float jf = (float)j, iff = (float)i;
    float rcx[2] = {v0.z, v1.z}, rcy[2] = {v0.w, v1.w};
    float rw[2]  = {v1.x, v2.x}, rh[2]  = {v1.y, v2.y};
    #pragma unroll
    for (int a = 0; a < 2; a++){
        float cx = __fmul_rn(__fadd_rn(rcx[a], jf), 16.0f);
        float cy = __fmul_rn(__fadd_rn(rcy[a], iff), 16.0f);
        float w = rw[a], h = rh[a];
        if (sq){ w = __fmul_rn(w, w); h = __fmul_rn(h, h); }
        w = __fmul_rn(w, 8192.0f);
        h = __fmul_rn(h, 8192.0f);
        int idx = cell*2 + a;
        ((float4*)out)[idx] = make_float4(cx, cy, w, h);
    }
}

// ---------------- launch (all nodes PDL-chained) ----------------
template <typename... Args>
static inline void pdl_launch(void (*kern)(Args...), dim3 grid, dim3 block,
                              size_t smem, Args... args){
    cudaLaunchConfig_t cfg = {};
    cfg.gridDim = grid;
    cfg.blockDim = block;
    cfg.dynamicSmemBytes = smem;
    cudaLaunchAttribute attr[1];
    attr[0].id = cudaLaunchAttributeProgrammaticStreamSerialization;
    attr[0].val.programmaticStreamSerializationAllowed = 1;
    cfg.attrs = attr;
    cfg.numAttrs = 1;
    cudaLaunchKernelEx(&cfg, kern, args...);
}

extern "C" void kernel_launch(void* const* d_in, const int* in_sizes, int n_in,
                              void* d_out, int out_size){
    const float* in = (const float*)d_in[0];
    const int*   sq = (const int*)d_in[1];

    if (out_size >= NBOX*4){
        k_rawboxes<<<NCELLS/256, 256>>>(in, sq, (float*)d_out);
        return;
    }

    cudaFuncSetAttribute(k_final, cudaFuncAttributeMaxDynamicSharedMemorySize, SMEM_FIN);

    pdl_launch(k_decode, dim3((NCELLS*4)/256), dim3(256), 0, in, sq);
    pdl_launch(k_scan, dim3(1), dim3(1024), (size_t)0);
    pdl_launch(k_scatter, dim3(NBOX/256), dim3(256), (size_t)0);
    pdl_launch(k_rank, dim3(64), dim3(256), (size_t)0);
    pdl_launch(k_matrix, dim3(148), dim3(128), (size_t)0);
    pdl_launch(k_final, dim3(1), dim3(512), (size_t)SMEM_FIN,
               in, (float*)d_out, out_size);
}